// round 6
// baseline (speedup 1.0000x reference)
#include <cuda_runtime.h>

// Grid_nd_sample: bilinear interpolation gather.
// in_tensor: (B=16, H=128, W=128, C=256) fp32  (268 MB)
// indices:   (B, P=8192, 2) fp32
// out:       (B, P, C) fp32  (134 MB)
//
// DRAM traffic is at the compulsory floor (~338 MB); perf scales with
// achieved bandwidth, which scales with per-thread MLP. This round:
// 4 points per thread -> 16 independent front-batched 16B gathers.

namespace {
constexpr int B = 16;
constexpr int H = 128;
constexpr int W = 128;
constexpr int C = 256;
constexpr int P = 8192;
constexpr int C4 = C / 4;                       // 64 float4 chunks per point
constexpr long NQUAD = (long)B * P / 4;         // 32768 point-quads
constexpr long TOTAL = NQUAD * C4;              // 2,097,152 threads
}

__global__ __launch_bounds__(128) void grid_sample_kernel(
    const float* __restrict__ in,
    const float* __restrict__ idx,
    float* __restrict__ out)
{
    long i = (long)blockIdx.x * blockDim.x + threadIdx.x;
    if (i >= TOTAL) return;

    int  c4   = (int)(i & (C4 - 1));   // 0..63
    long quad = i >> 6;                // quad id
    long bp0  = quad * 4;              // first point of the quad
    int  b    = (int)(bp0 >> 13);      // P = 8192 = 2^13; quad never spans images

    // Index loads: warp-uniform -> broadcast (8 floats = 4 points)
    float4 iA = __ldg((const float4*)(idx + bp0 * 2));
    float4 iB = __ldg((const float4*)(idx + bp0 * 2) + 1);

    float iy[4] = {iA.x, iA.z, iB.x, iB.z};
    float ix[4] = {iA.y, iA.w, iB.y, iB.w};

    int yl[4], yh[4], xl[4], xh[4];
    float muy[4], mux[4];
#pragma unroll
    for (int p = 0; p < 4; p++) {
        float fy = floorf(iy[p]), fx = floorf(ix[p]);
        yl[p] = (int)fy;         xl[p] = (int)fx;
        yh[p] = (int)ceilf(iy[p]); xh[p] = (int)ceilf(ix[p]);
        muy[p] = iy[p] - fy;     mux[p] = ix[p] - fx;
    }

    const long img = (long)b * H * W * C4;   // in units of float4
    const float4* base = (const float4*)in + img;

    // 16 independent gathers, front-batched for max MLP
    float4 v00[4], v10[4], v01[4], v11[4];
#pragma unroll
    for (int p = 0; p < 4; p++) {
        v00[p] = __ldg(base + ((long)yl[p] * W + xl[p]) * C4 + c4);
        v10[p] = __ldg(base + ((long)yh[p] * W + xl[p]) * C4 + c4);
        v01[p] = __ldg(base + ((long)yl[p] * W + xh[p]) * C4 + c4);
        v11[p] = __ldg(base + ((long)yh[p] * W + xh[p]) * C4 + c4);
    }

    float4* op = (float4*)(out + bp0 * C) + c4;
#pragma unroll
    for (int p = 0; p < 4; p++) {
        float w00 = (1.0f - muy[p]) * (1.0f - mux[p]);
        float w10 = muy[p] * (1.0f - mux[p]);
        float w01 = (1.0f - muy[p]) * mux[p];
        float w11 = muy[p] * mux[p];

        float4 o;
        o.x = v00[p].x * w00 + v10[p].x * w10 + v01[p].x * w01 + v11[p].x * w11;
        o.y = v00[p].y * w00 + v10[p].y * w10 + v01[p].y * w01 + v11[p].y * w11;
        o.z = v00[p].z * w00 + v10[p].z * w10 + v01[p].z * w01 + v11[p].z * w11;
        o.w = v00[p].w * w00 + v10[p].w * w10 + v01[p].w * w01 + v11[p].w * w11;
        op[(long)p * C4] = o;
    }
}

extern "C" void kernel_launch(void* const* d_in, const int* in_sizes, int n_in,
                              void* d_out, int out_size)
{
    const float* in_tensor = (const float*)d_in[0];
    const float* indices   = (const float*)d_in[1];
    float* out = (float*)d_out;

    const int threads = 128;
    const long blocks = (TOTAL + threads - 1) / threads;  // 16384
    grid_sample_kernel<<<(unsigned)blocks, threads>>>(in_tensor, indices, out);
}